// round 5
// baseline (speedup 1.0000x reference)
#include <cuda_runtime.h>

#define BB 512
#define SS 1024
#define TT 64
#define WARPS_PER_CTA 4
#define CTAS (BB / WARPS_PER_CTA)

// Precomputed shifted transition exponentials (step-invariant).
__device__ float g_E[TT * TT];     // E'[t][k] = exp(trans[t][k] - rowmax[t])
__device__ float g_rmax[TT];       // rowmax[t] = max_k trans[t][k]

// ---------------------------------------------------------------------------
// prep: E' = exp(trans - rowmax) ; one block per row t, 64 threads (2 warps)
// ---------------------------------------------------------------------------
__global__ void crf_prep_kernel(const float* __restrict__ trans) {
    int t = blockIdx.x;
    int k = threadIdx.x;
    float x = trans[t * TT + k];

    // warp max via ordered-int redux, then 2-warp combine through smem
    __shared__ float sm[2];
    int i = __float_as_int(x);
    i = (i >= 0) ? i : (i ^ 0x7FFFFFFF);
    i = __reduce_max_sync(0xFFFFFFFFu, i);
    float wm = __int_as_float((i >= 0) ? i : (i ^ 0x7FFFFFFF));
    if ((k & 31) == 0) sm[k >> 5] = wm;
    __syncthreads();
    float rmax = fmaxf(sm[0], sm[1]);

    g_E[t * TT + k] = __expf(x - rmax);
    if (k == 0) g_rmax[t] = rmax;
}

// ---------------------------------------------------------------------------
// packed f32x2 helpers (Blackwell-only packed fp32 pipe; PTX-only per quickref)
// ---------------------------------------------------------------------------
typedef unsigned long long u64;

__device__ __forceinline__ u64 pk2(float lo, float hi) {
    u64 r; asm("mov.b64 %0, {%1, %2};" : "=l"(r) : "f"(lo), "f"(hi)); return r;
}
__device__ __forceinline__ void upk2(float& lo, float& hi, u64 v) {
    asm("mov.b64 {%0, %1}, %2;" : "=f"(lo), "=f"(hi) : "l"(v));
}
__device__ __forceinline__ u64 fma2(u64 a, u64 b, u64 c) {
    u64 d; asm("fma.rn.f32x2 %0, %1, %2, %3;" : "=l"(d) : "l"(a), "l"(b), "l"(c));
    return d;
}
__device__ __forceinline__ u64 add2(u64 a, u64 b) {
    u64 d; asm("add.rn.f32x2 %0, %1, %2;" : "=l"(d) : "l"(a), "l"(b));
    return d;
}

// warp-wide float max via monotone int mapping + single REDUX
__device__ __forceinline__ float warp_fmax(float x) {
    int i = __float_as_int(x);
    i = (i >= 0) ? i : (i ^ 0x7FFFFFFF);
    i = __reduce_max_sync(0xFFFFFFFFu, i);
    return __int_as_float((i >= 0) ? i : (i ^ 0x7FFFFFFF));
}

// ---------------------------------------------------------------------------
// main scan: one warp per batch; lane owns states (lane, lane+32)
// ---------------------------------------------------------------------------
__global__ void __launch_bounds__(128, 1) crf_scan_kernel(
    const float* __restrict__ feats,   // [B, S, T]
    const float* __restrict__ masks,   // [B, S]
    float* __restrict__ out)           // [B, T]
{
    const int wid  = threadIdx.x >> 5;
    const int lane = threadIdx.x & 31;
    const int b    = blockIdx.x * WARPS_PER_CTA + wid;
    const int t0 = lane, t1 = lane + 32;

    // per-warp double-buffered v exchange (broadcast reads -> conflict-free)
    __shared__ __align__(16) float vbuf[WARPS_PER_CTA][2][TT];

    // E' rows for this lane's two states, packed as f32x2 pairs (128 regs)
    u64 e0[32], e1[32];
    {
        const float4* r0p = (const float4*)(g_E + t0 * TT);
        const float4* r1p = (const float4*)(g_E + t1 * TT);
#pragma unroll
        for (int j = 0; j < 16; j++) {
            float4 a = r0p[j];
            e0[2 * j]     = pk2(a.x, a.y);
            e0[2 * j + 1] = pk2(a.z, a.w);
            float4 c = r1p[j];
            e1[2 * j]     = pk2(c.x, c.y);
            e1[2 * j + 1] = pk2(c.z, c.w);
        }
    }
    const float r0 = g_rmax[t0];
    const float r1 = g_rmax[t1];

    const float* fptr = feats + (long)b * SS * TT;
    const float* mptr = masks + (long)b * SS;

    // alpha0 = feats[:, 0, :]
    float a0 = fptr[t0];
    float a1 = fptr[t1];

    // distance-2 feats/mask prefetch pipeline (SS >= 3 guaranteed)
    float fA0 = __ldg(fptr + TT + t0),     fA1 = __ldg(fptr + TT + t1);
    float mA  = __ldg(mptr + 1);
    float fB0 = __ldg(fptr + 2 * TT + t0), fB1 = __ldg(fptr + 2 * TT + t1);
    float mB  = __ldg(mptr + 2);

    int p = 0;
    for (int i = 1; i < SS; i++) {
        // issue prefetch for step i+2
        float fC0 = 0.f, fC1 = 0.f, mC = 0.f;
        if (i + 2 < SS) {
            const float* fp = fptr + (i + 2) * TT;
            fC0 = __ldg(fp + t0);
            fC1 = __ldg(fp + t1);
            mC  = __ldg(mptr + i + 2);
        }

        // m = max_k alpha[k]   (1 FMNMX + 1 REDUX)
        float m = warp_fmax(fmaxf(a0, a1));

        // v = exp(alpha - m); publish to this warp's buffer
        float v0 = __expf(a0 - m);
        float v1 = __expf(a1 - m);
        float* vb = vbuf[wid][p];
        vb[t0] = v0;
        vb[t1] = v1;
        __syncwarp();

        // dot: sum_k v[k] * E'[t][k], packed pairs, 4 independent chains
        const ulonglong2* vv = (const ulonglong2*)vb;
        u64 A0 = pk2(0.f, 0.f), A1 = A0, B0 = A0, B1 = A0;
#pragma unroll
        for (int j = 0; j < 16; j++) {
            ulonglong2 q = vv[j];
            A0 = fma2(q.x, e0[2 * j],     A0);
            A1 = fma2(q.y, e0[2 * j + 1], A1);
            B0 = fma2(q.x, e1[2 * j],     B0);
            B1 = fma2(q.y, e1[2 * j + 1], B1);
        }
        float s0lo, s0hi, s1lo, s1hi;
        upk2(s0lo, s0hi, add2(A0, A1));
        upk2(s1lo, s1hi, add2(B0, B1));
        float sum0 = s0lo + s0hi;
        float sum1 = s1lo + s1hi;

        // new alpha = feat + m + rowmax + log(sum) ; mask blend as in reference
        float n0 = fA0 + m + r0 + __logf(sum0);
        float n1 = fA1 + m + r1 + __logf(sum1);
        a0 = n0 * mA + a0 * (1.0f - mA);
        a1 = n1 * mA + a1 * (1.0f - mA);

        // rotate prefetch registers
        fA0 = fB0; fA1 = fB1; mA = mB;
        fB0 = fC0; fB1 = fC1; mB = mC;
        p ^= 1;
    }

    out[b * TT + t0] = a0;
    out[b * TT + t1] = a1;
}

// ---------------------------------------------------------------------------
// launch
// ---------------------------------------------------------------------------
extern "C" void kernel_launch(void* const* d_in, const int* in_sizes, int n_in,
                              void* d_out, int out_size) {
    const float* feats = (const float*)d_in[0];  // [512, 1024, 64]
    const float* masks = (const float*)d_in[1];  // [512, 1024]
    const float* trans = (const float*)d_in[2];  // [64, 64]
    float* out = (float*)d_out;                  // [512, 64]

    crf_prep_kernel<<<TT, TT>>>(trans);
    crf_scan_kernel<<<CTAS, WARPS_PER_CTA * 32>>>(feats, masks, out);
}